// round 4
// baseline (speedup 1.0000x reference)
#include <cuda_runtime.h>

// PointPillarScatter: out[b][c][y][x] = feat[p][c] where coords[p] = (x, y, b), else 0.
// Shapes fixed by the problem: NX=432, NY=496, C=64, B=4, P = in_sizes[0]/64.
#define NXc 432
#define NYc 496
#define Cc  64
#define Bc  4
#define XQ  (NXc / 4)          // 108 float4 per x-row
#define GRID_CELLS (Bc * NYc * NXc)   // 857088

// Scratch: pillar-id lookup grid (3.4 MB) + coord-dtype flag. __device__ globals
// (no allocation allowed anywhere).
__device__ int g_pid[GRID_CELLS];
__device__ int g_is64;

// ---------------------------------------------------------------------------
// 1) Detect coord dtype. int64 little-endian with small positive values =>
//    every odd 32-bit word is zero. int32 layout => odd words hold y/x/b values
//    (y uniform in [0,496)) and are essentially never all zero across 4096
//    samples. Both candidate buffers are >= 480 KB, so reading words [0, 8192)
//    is in-bounds either way. Runs every launch (deterministic).
// ---------------------------------------------------------------------------
__global__ void detect_dtype_kernel(const int* __restrict__ w) {
    int acc = 0;
    for (int i = threadIdx.x; i < 4096; i += blockDim.x)
        acc |= w[2 * i + 1];
    int any = __syncthreads_or(acc);
    if (threadIdx.x == 0)
        g_is64 = (any == 0) ? 1 : 0;
}

// ---------------------------------------------------------------------------
// 2) Reset lookup grid to -1 (int4-vectorized, 214272 stores).
// ---------------------------------------------------------------------------
__global__ void init_pid_kernel() {
    int i = blockIdx.x * blockDim.x + threadIdx.x;   // exactly GRID_CELLS/4 threads
    reinterpret_cast<int4*>(g_pid)[i] = make_int4(-1, -1, -1, -1);
}

// ---------------------------------------------------------------------------
// 3) Scatter pillar ids into the lookup grid (coords unique per batch => no
//    write conflicts).
// ---------------------------------------------------------------------------
__global__ void scatter_pid_kernel(const int* __restrict__ cw, int P) {
    int p = blockIdx.x * blockDim.x + threadIdx.x;
    if (p >= P) return;
    int x, y, b;
    if (g_is64) {                 // int64 coords: low words at even offsets
        x = cw[6 * p + 0];
        y = cw[6 * p + 2];
        b = cw[6 * p + 4];
    } else {                      // int32 coords
        x = cw[3 * p + 0];
        y = cw[3 * p + 1];
        b = cw[3 * p + 2];
    }
    g_pid[(b * NYc + y) * NXc + x] = p;
}

// ---------------------------------------------------------------------------
// 4) Gather pass: one thread owns one (b, y, x4) site across ALL 64 channels.
//    - pid lookup: one int4 load per thread (pid map read exactly once)
//    - feat: each valid pillar row (256 B) read exactly once, via LDG.128
//    - out: 64 STG.128 per thread, fully coalesced along x (warp = 512 B runs)
//    In-register 4x4 transpose converts pillar-major feat rows into
//    channel-major output vectors.
// ---------------------------------------------------------------------------
__global__ void gather_kernel(const float4* __restrict__ featv,
                              float4* __restrict__ outv) {
    int t  = blockIdx.x * blockDim.x + threadIdx.x;  // exactly B*NY*XQ threads
    int xq = t % XQ;
    int r  = t / XQ;
    int y  = r % NYc;
    int b  = r / NYc;

    int4 pid = reinterpret_cast<const int4*>(g_pid)[(b * NYc + y) * XQ + xq];

    int base = (b * Cc * NYc + y) * XQ + xq;         // float4 index of (b, c=0, y, x4)
    const int cstride = NYc * XQ;                    // 53568 float4 between channels
    const float4 z = make_float4(0.f, 0.f, 0.f, 0.f);

#pragma unroll 4
    for (int c4 = 0; c4 < Cc / 4; c4++) {
        // Four pillar feature quads (channels 4*c4 .. 4*c4+3), predicated loads.
        float4 f0 = (pid.x >= 0) ? featv[pid.x * (Cc / 4) + c4] : z;
        float4 f1 = (pid.y >= 0) ? featv[pid.y * (Cc / 4) + c4] : z;
        float4 f2 = (pid.z >= 0) ? featv[pid.z * (Cc / 4) + c4] : z;
        float4 f3 = (pid.w >= 0) ? featv[pid.w * (Cc / 4) + c4] : z;

        // 4x4 transpose: component j of each quad -> output vector for channel 4*c4+j.
        int o = base + (c4 * 4) * cstride;
        outv[o]               = make_float4(f0.x, f1.x, f2.x, f3.x);
        outv[o + cstride]     = make_float4(f0.y, f1.y, f2.y, f3.y);
        outv[o + 2 * cstride] = make_float4(f0.z, f1.z, f2.z, f3.z);
        outv[o + 3 * cstride] = make_float4(f0.w, f1.w, f2.w, f3.w);
    }
}

// ---------------------------------------------------------------------------
// Launch: 4 dependent kernels on the capture stream. No syncs, no allocs,
// no memcpys -> graph-capturable.
// ---------------------------------------------------------------------------
extern "C" void kernel_launch(void* const* d_in, const int* in_sizes, int n_in,
                              void* d_out, int out_size) {
    const float* feat = (const float*)d_in[0];
    const int*   cw   = (const int*)d_in[1];
    int P = in_sizes[0] / Cc;

    detect_dtype_kernel<<<1, 256>>>(cw);
    init_pid_kernel<<<GRID_CELLS / 4 / 256, 256>>>();                 // 837 blocks
    scatter_pid_kernel<<<(P + 255) / 256, 256>>>(cw, P);
    gather_kernel<<<(Bc * NYc * XQ) / 256, 256>>>(                    // 837 blocks
        (const float4*)feat, (float4*)d_out);
}

// round 5
// speedup vs baseline: 1.0876x; 1.0876x over previous
#include <cuda_runtime.h>

// PointPillarScatter: out[b][c][y][x] = feat[p][c] where coords[p] = (x, y, b), else 0.
#define NXc 432
#define NYc 496
#define Cc  64
#define Bc  4
#define XQ  (NXc / 4)                 // 108 float4 per x-row
#define GRID_CELLS (Bc * NYc * NXc)   // 857088

// Scratch (no allocation allowed): pillar-id lookup grid (3.4 MB) + dtype flag.
__device__ int g_pid[GRID_CELLS];
__device__ int g_is64;

// ---------------------------------------------------------------------------
// 1) Fused init + dtype detect.
//    All blocks: vectorized -1 fill of the pid grid (int4 stores).
//    Block 0 additionally: detect coord dtype. int64 little-endian with small
//    positive values => every odd 32-bit word is zero; int32 layout => odd
//    words hold y/x/b values and are essentially never all zero over 4096
//    samples. Coords buffer >= 480 KB either way, so words [0, 8192) are
//    in-bounds. Deterministic, runs every launch.
// ---------------------------------------------------------------------------
__global__ void init_detect_kernel(const int* __restrict__ cw) {
    int i = blockIdx.x * blockDim.x + threadIdx.x;   // exactly GRID_CELLS/4 threads
    reinterpret_cast<int4*>(g_pid)[i] = make_int4(-1, -1, -1, -1);

    if (blockIdx.x == 0) {
        int acc = 0;
        for (int k = threadIdx.x; k < 4096; k += blockDim.x)
            acc |= cw[2 * k + 1];
        int any = __syncthreads_or(acc);
        if (threadIdx.x == 0)
            g_is64 = (any == 0) ? 1 : 0;
    }
}

// ---------------------------------------------------------------------------
// 2) Scatter pillar ids into the lookup grid (coords unique per batch).
// ---------------------------------------------------------------------------
__global__ void scatter_pid_kernel(const int* __restrict__ cw, int P) {
    int p = blockIdx.x * blockDim.x + threadIdx.x;
    if (p >= P) return;
    int x, y, b;
    if (g_is64) {                 // int64 coords: low words at even offsets
        x = cw[6 * p + 0];
        y = cw[6 * p + 2];
        b = cw[6 * p + 4];
    } else {                      // int32 coords
        x = cw[3 * p + 0];
        y = cw[3 * p + 1];
        b = cw[3 * p + 2];
    }
    g_pid[(b * NYc + y) * NXc + x] = p;
}

// ---------------------------------------------------------------------------
// 3) Gather pass, one thread per (c4, b, y, x4) site: 4 random 16B feat loads
//    (L2-resident after first touch) + in-register 4x4 transpose + 4 perfectly
//    coalesced 16B stores to 4 channel planes. 3.43M threads -> full occupancy,
//    enough warps in flight to hide L2 latency behind the 219MB store stream.
//    pid map re-read per c4-group is pure L2 traffic (~54MB, negligible at the
//    ~6300 B/cyc LTS cap).
// ---------------------------------------------------------------------------
__global__ void __launch_bounds__(256) gather_kernel(const float4* __restrict__ featv,
                                                     float4* __restrict__ outv) {
    int t  = blockIdx.x * blockDim.x + threadIdx.x;  // exactly (Cc/4)*Bc*NYc*XQ threads
    int xq = t % XQ;
    int r  = t / XQ;
    int y  = r % NYc;
    r /= NYc;
    int b  = r % Bc;
    int c4 = r / Bc;                                 // 0..15

    int4 pid = reinterpret_cast<const int4*>(g_pid)[(b * NYc + y) * XQ + xq];

    const float4 z = make_float4(0.f, 0.f, 0.f, 0.f);
    // Channels 4*c4 .. 4*c4+3 of each of the 4 pillars at this x4 site.
    float4 f0 = (pid.x >= 0) ? __ldg(&featv[pid.x * (Cc / 4) + c4]) : z;
    float4 f1 = (pid.y >= 0) ? __ldg(&featv[pid.y * (Cc / 4) + c4]) : z;
    float4 f2 = (pid.z >= 0) ? __ldg(&featv[pid.z * (Cc / 4) + c4]) : z;
    float4 f3 = (pid.w >= 0) ? __ldg(&featv[pid.w * (Cc / 4) + c4]) : z;

    // 4x4 transpose: component j -> output vector for channel 4*c4+j.
    const int cstride = NYc * XQ;                    // float4s between channel planes
    int o = ((b * Cc + c4 * 4) * NYc + y) * XQ + xq;
    outv[o]               = make_float4(f0.x, f1.x, f2.x, f3.x);
    outv[o + cstride]     = make_float4(f0.y, f1.y, f2.y, f3.y);
    outv[o + 2 * cstride] = make_float4(f0.z, f1.z, f2.z, f3.z);
    outv[o + 3 * cstride] = make_float4(f0.w, f1.w, f2.w, f3.w);
}

// ---------------------------------------------------------------------------
// Launch: 3 dependent kernel nodes, graph-capturable (no syncs/allocs/memcpy).
// ---------------------------------------------------------------------------
extern "C" void kernel_launch(void* const* d_in, const int* in_sizes, int n_in,
                              void* d_out, int out_size) {
    const float* feat = (const float*)d_in[0];
    const int*   cw   = (const int*)d_in[1];
    int P = in_sizes[0] / Cc;

    init_detect_kernel<<<GRID_CELLS / 4 / 256, 256>>>(cw);            // 837 blocks
    scatter_pid_kernel<<<(P + 255) / 256, 256>>>(cw, P);
    gather_kernel<<<(Cc / 4) * Bc * NYc * XQ / 256, 256>>>(           // 13392 blocks
        (const float4*)feat, (float4*)d_out);
}

// round 6
// speedup vs baseline: 1.2664x; 1.1645x over previous
#include <cuda_runtime.h>

// PointPillarScatter: out[b][c][y][x] = feat[p][c] where coords[p] = (x, y, b), else 0.
#define NXc 432
#define NYc 496
#define Cc  64
#define Bc  4
#define XQ  (NXc / 4)                 // 108 float4 per x-row
#define GRID_CELLS (Bc * NYc * NXc)   // 857088

// Scratch (no allocation allowed): pillar-id lookup grid (3.4 MB).
__device__ int g_pid[GRID_CELLS];

// ---------------------------------------------------------------------------
// 1) Pure init: vectorized -1 fill of the pid grid. No detect tail — nothing
//    serializes this kernel anymore.
// ---------------------------------------------------------------------------
__global__ void init_pid_kernel() {
    int i = blockIdx.x * blockDim.x + threadIdx.x;   // exactly GRID_CELLS/4 threads
    reinterpret_cast<int4*>(g_pid)[i] = make_int4(-1, -1, -1, -1);
}

// ---------------------------------------------------------------------------
// 2) Scatter pillar ids, with PER-BLOCK inline coord-dtype detection.
//    int64 little-endian coords with small positive values => every odd 32-bit
//    word is zero; int32 layout => odd words hold y/x/b values and are never
//    all zero over 4096 samples of this dataset. Each block samples 256 odd
//    words from the first 32 KB of cw (in-bounds for either dtype: coords
//    buffer >= 480 KB) and OR-reduces locally. All blocks read the same 32 KB
//    => L2-hot after the first block; no serial one-block tail. Deterministic.
// ---------------------------------------------------------------------------
__global__ void scatter_pid_kernel(const int* __restrict__ cw, int P) {
    int p = blockIdx.x * blockDim.x + threadIdx.x;

    // Per-block dtype detect (all threads participate in the barrier).
    int s = p & 4095;                                // sample index 0..4095
    int w = __ldg(&cw[2 * s + 1]);
    int any = __syncthreads_or(w);
    int is64 = (any == 0);

    if (p >= P) return;
    int x, y, b;
    if (is64) {                   // int64 coords: low words at even offsets
        x = cw[6 * p + 0];
        y = cw[6 * p + 2];
        b = cw[6 * p + 4];
    } else {                      // int32 coords
        x = cw[3 * p + 0];
        y = cw[3 * p + 1];
        b = cw[3 * p + 2];
    }
    g_pid[(b * NYc + y) * NXc + x] = p;              // coords unique per batch
}

// ---------------------------------------------------------------------------
// 3) Gather pass, one thread per (c4, b, y, x4) site: 4 random 16B feat loads
//    + in-register 4x4 transpose + 4 coalesced 16B STREAMING stores (__stcs:
//    evict-first, so the 219MB output stream does not flush the 3.4MB pid map
//    and 10MB feat out of L2 -> random loads stay L2 hits -> less latency to
//    hide -> higher sustained store bandwidth). 3.43M threads, full occupancy.
// ---------------------------------------------------------------------------
__global__ void __launch_bounds__(256) gather_kernel(const float4* __restrict__ featv,
                                                     float4* __restrict__ outv) {
    int t  = blockIdx.x * blockDim.x + threadIdx.x;  // exactly (Cc/4)*Bc*NYc*XQ threads
    int xq = t % XQ;
    int r  = t / XQ;
    int y  = r % NYc;
    r /= NYc;
    int b  = r % Bc;
    int c4 = r / Bc;                                 // 0..15

    int4 pid = __ldg(&reinterpret_cast<const int4*>(g_pid)[(b * NYc + y) * XQ + xq]);

    const float4 z = make_float4(0.f, 0.f, 0.f, 0.f);
    // Channels 4*c4 .. 4*c4+3 of each of the 4 pillars at this x4 site.
    float4 f0 = (pid.x >= 0) ? __ldg(&featv[pid.x * (Cc / 4) + c4]) : z;
    float4 f1 = (pid.y >= 0) ? __ldg(&featv[pid.y * (Cc / 4) + c4]) : z;
    float4 f2 = (pid.z >= 0) ? __ldg(&featv[pid.z * (Cc / 4) + c4]) : z;
    float4 f3 = (pid.w >= 0) ? __ldg(&featv[pid.w * (Cc / 4) + c4]) : z;

    // 4x4 transpose: component j -> output vector for channel 4*c4+j.
    const int cstride = NYc * XQ;                    // float4s between channel planes
    int o = ((b * Cc + c4 * 4) * NYc + y) * XQ + xq;
    __stcs(&outv[o],               make_float4(f0.x, f1.x, f2.x, f3.x));
    __stcs(&outv[o + cstride],     make_float4(f0.y, f1.y, f2.y, f3.y));
    __stcs(&outv[o + 2 * cstride], make_float4(f0.z, f1.z, f2.z, f3.z));
    __stcs(&outv[o + 3 * cstride], make_float4(f0.w, f1.w, f2.w, f3.w));
}

// ---------------------------------------------------------------------------
// Launch: 3 dependent kernel nodes, graph-capturable (no syncs/allocs/memcpy).
// ---------------------------------------------------------------------------
extern "C" void kernel_launch(void* const* d_in, const int* in_sizes, int n_in,
                              void* d_out, int out_size) {
    const float* feat = (const float*)d_in[0];
    const int*   cw   = (const int*)d_in[1];
    int P = in_sizes[0] / Cc;

    init_pid_kernel<<<GRID_CELLS / 4 / 256, 256>>>();                 // 837 blocks
    scatter_pid_kernel<<<(P + 255) / 256, 256>>>(cw, P);
    gather_kernel<<<(Cc / 4) * Bc * NYc * XQ / 256, 256>>>(           // 13392 blocks
        (const float4*)feat, (float4*)d_out);
}